// round 1
// baseline (speedup 1.0000x reference)
#include <cuda_runtime.h>

// FwFM second-order: out[i] = sum_{k<l} S[k,l] * x[k,i] * x[l,i],
// S = 0.5*(W + W^T), i ranges over B*D = 524288 contiguous elements per field k.

#define KF 39
#define NELEM (8192 * 64)        // B*D = 524288
#define NPAIR (NELEM / 2)        // float2 elements = 262144
#define THREADS 256

__global__ __launch_bounds__(THREADS)
void fwfm_kernel(const float* __restrict__ x,
                 const float* __restrict__ W,
                 float* __restrict__ out) {
    __shared__ float Ssh[KF * KF];

    // Symmetrize W into shared (broadcast-read later, conflict-free).
    for (int i = threadIdx.x; i < KF * KF; i += THREADS) {
        int r = i / KF;
        int c = i - r * KF;
        Ssh[i] = 0.5f * (W[r * KF + c] + W[c * KF + r]);
    }
    __syncthreads();

    int i = blockIdx.x * THREADS + threadIdx.x;   // float2 index, exact grid

    // Front-batched coalesced loads: 39 x LDG.64, stride NELEM floats between fields.
    const float2* __restrict__ xp = reinterpret_cast<const float2*>(x);
    float2 v[KF];
#pragma unroll
    for (int k = 0; k < KF; ++k) {
        v[k] = xp[(size_t)k * NPAIR + i];
    }

    float y0 = 0.0f, y1 = 0.0f;
    // Strict-upper-triangle bilinear form, factored: y += v_l * (sum_{k<l} S[k,l] v_k).
    // Fully unrolled (K compile-time) -> LDS with immediate offsets, 780 FMAs/elem.
#pragma unroll
    for (int l = 1; l < KF; ++l) {
        float t0 = 0.0f, t1 = 0.0f;
#pragma unroll
        for (int k = 0; k < l; ++k) {
            float s = Ssh[l * KF + k];
            t0 = fmaf(s, v[k].x, t0);
            t1 = fmaf(s, v[k].y, t1);
        }
        y0 = fmaf(v[l].x, t0, y0);
        y1 = fmaf(v[l].y, t1, y1);
    }

    reinterpret_cast<float2*>(out)[i] = make_float2(y0, y1);
}

extern "C" void kernel_launch(void* const* d_in, const int* in_sizes, int n_in,
                              void* d_out, int out_size) {
    const float* x = (const float*)d_in[0];   // [39, 8192, 64] fp32
    const float* W = (const float*)d_in[1];   // [39, 39] fp32
    float* out = (float*)d_out;               // [8192, 64] fp32

    fwfm_kernel<<<NPAIR / THREADS, THREADS>>>(x, W, out);
}